// round 1
// baseline (speedup 1.0000x reference)
#include <cuda_runtime.h>
#include <mma.h>

using namespace nvcuda;

#define NB    16
#define LSEQ  2048
#define DDIM  1024

#define BM 128
#define BN 64
#define BK 16
#define LDA (BK + 4)   // 20, multiple of 4 for wmma tf32
#define LDV (BN + 4)   // 68, multiple of 4

// 256 MB scratch for scores/probs: S[b, q, k]
__device__ float g_S[(size_t)NB * LSEQ * LSEQ];

// ---------------------------------------------------------------------------
// Kernel 1: S = Q @ K^T  (per batch), tf32 WMMA, skip fully-masked tiles
// ---------------------------------------------------------------------------
__global__ __launch_bounds__(256) void qk_kernel(const float* __restrict__ Q,
                                                 const float* __restrict__ Kin) {
    const int n0 = blockIdx.x * BN;   // key index
    const int m0 = blockIdx.y * BM;   // query index
    const int b  = blockIdx.z;
    if (n0 > m0 + BM - 1) return;     // tile entirely above diagonal -> masked

    __shared__ float As[BM * LDA];
    __shared__ float Bs[BN * LDA];

    const float* Qb = Q   + (size_t)b * LSEQ * DDIM;
    const float* Kb = Kin + (size_t)b * LSEQ * DDIM;
    float*       Sb = g_S + (size_t)b * LSEQ * LSEQ;

    const int tid = threadIdx.x;
    const int wid = tid >> 5;
    const int wm  = (wid & 3) * 32;   // 4 warps along M
    const int wn  = (wid >> 2) * 32;  // 2 warps along N

    wmma::fragment<wmma::accumulator, 16, 16, 8, float> c[2][2];
#pragma unroll
    for (int i = 0; i < 2; i++)
#pragma unroll
        for (int j = 0; j < 2; j++) wmma::fill_fragment(c[i][j], 0.0f);

    for (int d0 = 0; d0 < DDIM; d0 += BK) {
        // Q tile: 128 x 16  (512 float4 loads, 2 per thread)
#pragma unroll
        for (int it = 0; it < 2; it++) {
            int i = tid + it * 256;
            int row = i >> 2, ch = (i & 3) * 4;
            *(float4*)&As[row * LDA + ch] =
                *(const float4*)(Qb + (size_t)(m0 + row) * DDIM + d0 + ch);
        }
        // K tile: 64 x 16  (256 float4 loads, 1 per thread)
        {
            int row = tid >> 2, ch = (tid & 3) * 4;
            *(float4*)&Bs[row * LDA + ch] =
                *(const float4*)(Kb + (size_t)(n0 + row) * DDIM + d0 + ch);
        }
        __syncthreads();

#pragma unroll
        for (int kk = 0; kk < BK; kk += 8) {
            wmma::fragment<wmma::matrix_a, 16, 16, 8, wmma::precision::tf32, wmma::row_major> a[2];
            wmma::fragment<wmma::matrix_b, 16, 16, 8, wmma::precision::tf32, wmma::col_major> bf[2];
#pragma unroll
            for (int i = 0; i < 2; i++) {
                wmma::load_matrix_sync(a[i], &As[(wm + i * 16) * LDA + kk], LDA);
#pragma unroll
                for (int t = 0; t < a[i].num_elements; t++)
                    a[i].x[t] = wmma::__float_to_tf32(a[i].x[t]);
            }
#pragma unroll
            for (int j = 0; j < 2; j++) {
                wmma::load_matrix_sync(bf[j], &Bs[(wn + j * 16) * LDA + kk], LDA);
#pragma unroll
                for (int t = 0; t < bf[j].num_elements; t++)
                    bf[j].x[t] = wmma::__float_to_tf32(bf[j].x[t]);
            }
#pragma unroll
            for (int i = 0; i < 2; i++)
#pragma unroll
                for (int j = 0; j < 2; j++)
                    wmma::mma_sync(c[i][j], a[i], bf[j], c[i][j]);
        }
        __syncthreads();
    }

#pragma unroll
    for (int i = 0; i < 2; i++)
#pragma unroll
        for (int j = 0; j < 2; j++)
            wmma::store_matrix_sync(Sb + (size_t)(m0 + wm + i * 16) * LSEQ + (n0 + wn + j * 16),
                                    c[i][j], LSEQ, wmma::mem_row_major);
}

// ---------------------------------------------------------------------------
// Kernel 2: row softmax of S/32 with causal mask; masked entries -> exact 0
// ---------------------------------------------------------------------------
__global__ __launch_bounds__(256) void softmax_kernel() {
    const int q = blockIdx.x;
    const int b = blockIdx.y;
    float* row = g_S + ((size_t)b * LSEQ + q) * LSEQ;

    const int tid = threadIdx.x;
    const float inv_scale = 1.0f / 32.0f;

    float v[8];
    float mx = -1e30f;
#pragma unroll
    for (int j = 0; j < 8; j++) {
        int i = tid + j * 256;
        float s = (i <= q) ? row[i] * inv_scale : -1e30f;
        v[j] = s;
        mx = fmaxf(mx, s);
    }

    __shared__ float red[8];
    // max reduce
#pragma unroll
    for (int o = 16; o > 0; o >>= 1) mx = fmaxf(mx, __shfl_xor_sync(0xFFFFFFFFu, mx, o));
    if ((tid & 31) == 0) red[tid >> 5] = mx;
    __syncthreads();
    float m = red[0];
#pragma unroll
    for (int w = 1; w < 8; w++) m = fmaxf(m, red[w]);
    __syncthreads();

    float sum = 0.0f;
#pragma unroll
    for (int j = 0; j < 8; j++) {
        float e = exp2f((v[j] - m) * 1.4426950408889634f);  // masked: exp2(-huge)=0
        v[j] = e;
        sum += e;
    }
#pragma unroll
    for (int o = 16; o > 0; o >>= 1) sum += __shfl_xor_sync(0xFFFFFFFFu, sum, o);
    if ((tid & 31) == 0) red[tid >> 5] = sum;
    __syncthreads();
    float tot = 0.0f;
#pragma unroll
    for (int w = 0; w < 8; w++) tot += red[w];
    const float r = 1.0f / tot;

#pragma unroll
    for (int j = 0; j < 8; j++) {
        int i = tid + j * 256;
        row[i] = v[j] * r;   // masked entries: 0 * r = 0 exactly
    }
}

// ---------------------------------------------------------------------------
// Kernel 3: O = P @ V (per batch), tf32 WMMA, K-trip truncated at diagonal
// ---------------------------------------------------------------------------
__global__ __launch_bounds__(256) void pv_kernel(const float* __restrict__ V,
                                                 float* __restrict__ O) {
    const int n0 = blockIdx.x * BN;   // head dim
    const int m0 = blockIdx.y * BM;   // query index
    const int b  = blockIdx.z;

    __shared__ float As[BM * LDA];
    __shared__ float Vs[BK * LDV];

    const float* Pb = g_S + (size_t)b * LSEQ * LSEQ;
    const float* Vb = V   + (size_t)b * LSEQ * DDIM;
    float*       Ob = O   + (size_t)b * LSEQ * DDIM;

    const int tid = threadIdx.x;
    const int wid = tid >> 5;
    const int wm  = (wid & 3) * 32;
    const int wn  = (wid >> 2) * 32;

    wmma::fragment<wmma::accumulator, 16, 16, 8, float> c[2][2];
#pragma unroll
    for (int i = 0; i < 2; i++)
#pragma unroll
        for (int j = 0; j < 2; j++) wmma::fill_fragment(c[i][j], 0.0f);

    const int ktiles = (m0 + BM) / BK;   // P[q,k] == 0 for k > q
    for (int t = 0; t < ktiles; t++) {
        const int k0 = t * BK;
        // P tile: 128 x 16
#pragma unroll
        for (int it = 0; it < 2; it++) {
            int i = tid + it * 256;
            int row = i >> 2, ch = (i & 3) * 4;
            *(float4*)&As[row * LDA + ch] =
                *(const float4*)(Pb + (size_t)(m0 + row) * LSEQ + k0 + ch);
        }
        // V tile: 16 x 64
        {
            int row = tid >> 4, ch = (tid & 15) * 4;
            *(float4*)&Vs[row * LDV + ch] =
                *(const float4*)(Vb + (size_t)(k0 + row) * DDIM + n0 + ch);
        }
        __syncthreads();

#pragma unroll
        for (int kk = 0; kk < BK; kk += 8) {
            wmma::fragment<wmma::matrix_a, 16, 16, 8, wmma::precision::tf32, wmma::row_major> a[2];
            wmma::fragment<wmma::matrix_b, 16, 16, 8, wmma::precision::tf32, wmma::row_major> bf[2];
#pragma unroll
            for (int i = 0; i < 2; i++) {
                wmma::load_matrix_sync(a[i], &As[(wm + i * 16) * LDA + kk], LDA);
#pragma unroll
                for (int t2 = 0; t2 < a[i].num_elements; t2++)
                    a[i].x[t2] = wmma::__float_to_tf32(a[i].x[t2]);
            }
#pragma unroll
            for (int j = 0; j < 2; j++) {
                wmma::load_matrix_sync(bf[j], &Vs[kk * LDV + wn + j * 16], LDV);
#pragma unroll
                for (int t2 = 0; t2 < bf[j].num_elements; t2++)
                    bf[j].x[t2] = wmma::__float_to_tf32(bf[j].x[t2]);
            }
#pragma unroll
            for (int i = 0; i < 2; i++)
#pragma unroll
                for (int j = 0; j < 2; j++)
                    wmma::mma_sync(c[i][j], a[i], bf[j], c[i][j]);
        }
        __syncthreads();
    }

#pragma unroll
    for (int i = 0; i < 2; i++)
#pragma unroll
        for (int j = 0; j < 2; j++)
            wmma::store_matrix_sync(Ob + (size_t)(m0 + wm + i * 16) * DDIM + (n0 + wn + j * 16),
                                    c[i][j], DDIM, wmma::mem_row_major);
}

// ---------------------------------------------------------------------------
extern "C" void kernel_launch(void* const* d_in, const int* in_sizes, int n_in,
                              void* d_out, int out_size) {
    const float* Q = (const float*)d_in[0];
    const float* K = (const float*)d_in[1];
    const float* V = (const float*)d_in[2];
    float* O = (float*)d_out;

    dim3 gQK(LSEQ / BN, LSEQ / BM, NB);    // 32 x 16 x 16
    qk_kernel<<<gQK, 256>>>(Q, K);

    dim3 gSM(LSEQ, NB);                    // 2048 x 16
    softmax_kernel<<<gSM, 256>>>();

    dim3 gPV(DDIM / BN, LSEQ / BM, NB);    // 16 x 16 x 16
    pv_kernel<<<gPV, 256>>>(V, O);
}

// round 3
// speedup vs baseline: 1.0380x; 1.0380x over previous
#include <cuda_runtime.h>
#include <mma.h>
#include <cstdint>

using namespace nvcuda;

#define NB    16
#define LSEQ  2048
#define DDIM  1024

#define BM 128
#define BN 64
#define BK 16
#define LDA (BK + 4)   // 20 floats, multiple of 4
#define LDV (BN + 4)   // 68 floats

// 256 MB scratch for scores/probs: S[b, q, k]
__device__ float g_S[(size_t)NB * LSEQ * LSEQ];

__device__ __forceinline__ float to_tf32(float x) {   // RN round to tf32
    float r;
    asm("cvt.rna.tf32.f32 %0, %1;" : "=f"(r) : "f"(x));
    return r;
}
__device__ __forceinline__ float4 to_tf32_4(float4 v) {
    v.x = to_tf32(v.x); v.y = to_tf32(v.y); v.z = to_tf32(v.z); v.w = to_tf32(v.w);
    return v;
}

// ---------------------------------------------------------------------------
// Kernel 1: S = Q @ K^T  (per batch), tf32 WMMA, double-buffered pipeline
// ---------------------------------------------------------------------------
__global__ __launch_bounds__(256) void qk_kernel(const float* __restrict__ Q,
                                                 const float* __restrict__ Kin) {
    const int n0 = blockIdx.x * BN;
    const int m0 = blockIdx.y * BM;
    const int b  = blockIdx.z;
    if (n0 > m0 + BM - 1) return;     // fully masked tile

    __shared__ float As[2][BM * LDA];
    __shared__ float Bs[2][BN * LDA];

    const float* Qb = Q   + (size_t)b * LSEQ * DDIM;
    const float* Kb = Kin + (size_t)b * LSEQ * DDIM;
    float*       Sb = g_S + (size_t)b * LSEQ * LSEQ;

    const int tid = threadIdx.x;
    const int wid = tid >> 5;
    const int wm  = (wid & 3) * 32;
    const int wn  = (wid >> 2) * 32;

    // per-thread load coordinates
    const int arow0 = tid >> 2, ach = (tid & 3) * 4;          // A: 2 rows/thread
    const int brow  = tid >> 2, bch = (tid & 3) * 4;          // B: 1 row/thread

    wmma::fragment<wmma::accumulator, 16, 16, 8, float> c[2][2];
#pragma unroll
    for (int i = 0; i < 2; i++)
#pragma unroll
        for (int j = 0; j < 2; j++) wmma::fill_fragment(c[i][j], 0.0f);

    float4 ra0, ra1, rb;
    // prologue: tile 0
    ra0 = *(const float4*)(Qb + (size_t)(m0 + arow0) * DDIM + 0 + ach);
    ra1 = *(const float4*)(Qb + (size_t)(m0 + arow0 + 64) * DDIM + 0 + ach);
    rb  = *(const float4*)(Kb + (size_t)(n0 + brow) * DDIM + 0 + bch);
    *(float4*)&As[0][arow0 * LDA + ach]        = to_tf32_4(ra0);
    *(float4*)&As[0][(arow0 + 64) * LDA + ach] = to_tf32_4(ra1);
    *(float4*)&Bs[0][brow * LDA + bch]         = to_tf32_4(rb);
    __syncthreads();

    const int nt = DDIM / BK;   // 64
    for (int it = 0; it < nt; ++it) {
        const int s = it & 1;
        if (it + 1 < nt) {
            const int d0 = (it + 1) * BK;
            ra0 = *(const float4*)(Qb + (size_t)(m0 + arow0) * DDIM + d0 + ach);
            ra1 = *(const float4*)(Qb + (size_t)(m0 + arow0 + 64) * DDIM + d0 + ach);
            rb  = *(const float4*)(Kb + (size_t)(n0 + brow) * DDIM + d0 + bch);
        }

#pragma unroll
        for (int kk = 0; kk < BK; kk += 8) {
            wmma::fragment<wmma::matrix_a, 16, 16, 8, wmma::precision::tf32, wmma::row_major> a[2];
            wmma::fragment<wmma::matrix_b, 16, 16, 8, wmma::precision::tf32, wmma::col_major> bf[2];
#pragma unroll
            for (int i = 0; i < 2; i++)
                wmma::load_matrix_sync(a[i], &As[s][(wm + i * 16) * LDA + kk], LDA);
#pragma unroll
            for (int j = 0; j < 2; j++)
                wmma::load_matrix_sync(bf[j], &Bs[s][(wn + j * 16) * LDA + kk], LDA);
#pragma unroll
            for (int i = 0; i < 2; i++)
#pragma unroll
                for (int j = 0; j < 2; j++)
                    wmma::mma_sync(c[i][j], a[i], bf[j], c[i][j]);
        }

        if (it + 1 < nt) {
            const int s1 = s ^ 1;
            *(float4*)&As[s1][arow0 * LDA + ach]        = to_tf32_4(ra0);
            *(float4*)&As[s1][(arow0 + 64) * LDA + ach] = to_tf32_4(ra1);
            *(float4*)&Bs[s1][brow * LDA + bch]         = to_tf32_4(rb);
            __syncthreads();
        }
    }

#pragma unroll
    for (int i = 0; i < 2; i++)
#pragma unroll
        for (int j = 0; j < 2; j++)
            wmma::store_matrix_sync(Sb + (size_t)(m0 + wm + i * 16) * LSEQ + (n0 + wn + j * 16),
                                    c[i][j], LSEQ, wmma::mem_row_major);
}

// ---------------------------------------------------------------------------
// Kernel 2: row softmax of S/32 with causal mask; masked entries -> exact 0
// ---------------------------------------------------------------------------
__global__ __launch_bounds__(256) void softmax_kernel() {
    const int q = blockIdx.x;
    const int b = blockIdx.y;
    float* row = g_S + ((size_t)b * LSEQ + q) * LSEQ;
    const int tid = threadIdx.x;

    float v[8];
    float mx = -1e30f;
#pragma unroll
    for (int j = 0; j < 8; j++) {
        int i = tid + j * 256;
        float s = (i <= q) ? row[i] * (1.0f / 32.0f) : -1e30f;
        v[j] = s;
        mx = fmaxf(mx, s);
    }
    __shared__ float red[8];
#pragma unroll
    for (int o = 16; o > 0; o >>= 1) mx = fmaxf(mx, __shfl_xor_sync(0xFFFFFFFFu, mx, o));
    if ((tid & 31) == 0) red[tid >> 5] = mx;
    __syncthreads();
    float m = red[0];
#pragma unroll
    for (int w = 1; w < 8; w++) m = fmaxf(m, red[w]);
    __syncthreads();

    float sum = 0.0f;
#pragma unroll
    for (int j = 0; j < 8; j++) {
        float e = exp2f((v[j] - m) * 1.4426950408889634f);
        v[j] = e;
        sum += e;
    }
#pragma unroll
    for (int o = 16; o > 0; o >>= 1) sum += __shfl_xor_sync(0xFFFFFFFFu, sum, o);
    if ((tid & 31) == 0) red[tid >> 5] = sum;
    __syncthreads();
    float tot = 0.0f;
#pragma unroll
    for (int w = 0; w < 8; w++) tot += red[w];
    const float r = 1.0f / tot;
#pragma unroll
    for (int j = 0; j < 8; j++) row[tid + j * 256] = v[j] * r;
}

// ---------------------------------------------------------------------------
// Kernel 3: O = P @ V (per batch), tf32 WMMA, double-buffered, causal K-trip
// ---------------------------------------------------------------------------
__global__ __launch_bounds__(256) void pv_kernel(const float* __restrict__ V,
                                                 float* __restrict__ O) {
    const int n0 = blockIdx.x * BN;   // head dim
    const int m0 = blockIdx.y * BM;
    const int b  = blockIdx.z;

    __shared__ float As[2][BM * LDA];
    __shared__ float Vs[2][BK * LDV];

    const float* Pb = g_S + (size_t)b * LSEQ * LSEQ;
    const float* Vb = V   + (size_t)b * LSEQ * DDIM;
    float*       Ob = O   + (size_t)b * LSEQ * DDIM;

    const int tid = threadIdx.x;
    const int wid = tid >> 5;
    const int wm  = (wid & 3) * 32;
    const int wn  = (wid >> 2) * 32;

    const int arow0 = tid >> 2, ach = (tid & 3) * 4;
    const int vrow  = tid >> 4, vch = (tid & 15) * 4;

    wmma::fragment<wmma::accumulator, 16, 16, 8, float> c[2][2];
#pragma unroll
    for (int i = 0; i < 2; i++)
#pragma unroll
        for (int j = 0; j < 2; j++) wmma::fill_fragment(c[i][j], 0.0f);

    float4 ra0, ra1, rv;
    ra0 = *(const float4*)(Pb + (size_t)(m0 + arow0) * LSEQ + 0 + ach);
    ra1 = *(const float4*)(Pb + (size_t)(m0 + arow0 + 64) * LSEQ + 0 + ach);
    rv  = *(const float4*)(Vb + (size_t)(0 + vrow) * DDIM + n0 + vch);
    *(float4*)&As[0][arow0 * LDA + ach]        = to_tf32_4(ra0);
    *(float4*)&As[0][(arow0 + 64) * LDA + ach] = to_tf32_4(ra1);
    *(float4*)&Vs[0][vrow * LDV + vch]         = to_tf32_4(rv);
    __syncthreads();

    const int nt = (m0 + BM) / BK;    // P[q,k]==0 for k>q
    for (int it = 0; it < nt; ++it) {
        const int s = it & 1;
        if (it + 1 < nt) {
            const int k0 = (it + 1) * BK;
            ra0 = *(const float4*)(Pb + (size_t)(m0 + arow0) * LSEQ + k0 + ach);
            ra1 = *(const float4*)(Pb + (size_t)(m0 + arow0 + 64) * LSEQ + k0 + ach);
            rv  = *(const float4*)(Vb + (size_t)(k0 + vrow) * DDIM + n0 + vch);
        }

#pragma unroll
        for (int kk = 0; kk < BK; kk += 8) {
            wmma::fragment<wmma::matrix_a, 16, 16, 8, wmma::precision::tf32, wmma::row_major> a[2];
            wmma::fragment<wmma::matrix_b, 16, 16, 8, wmma::precision::tf32, wmma::row_major> bf[2];
#pragma unroll
            for (int i = 0; i < 2; i++)
                wmma::load_matrix_sync(a[i], &As[s][(wm + i * 16) * LDA + kk], LDA);
#pragma unroll
            for (int j = 0; j < 2; j++)
                wmma::load_matrix_sync(bf[j], &Vs[s][kk * LDV + wn + j * 16], LDV);
#pragma unroll
            for (int i = 0; i < 2; i++)
#pragma unroll
                for (int j = 0; j < 2; j++)
                    wmma::mma_sync(c[i][j], a[i], bf[j], c[i][j]);
        }

        if (it + 1 < nt) {
            const int s1 = s ^ 1;
            *(float4*)&As[s1][arow0 * LDA + ach]        = to_tf32_4(ra0);
            *(float4*)&As[s1][(arow0 + 64) * LDA + ach] = to_tf32_4(ra1);
            *(float4*)&Vs[s1][vrow * LDV + vch]         = to_tf32_4(rv);
            __syncthreads();
        }
    }

#pragma unroll
    for (int i = 0; i < 2; i++)
#pragma unroll
        for (int j = 0; j < 2; j++)
            wmma::store_matrix_sync(Ob + (size_t)(m0 + wm + i * 16) * DDIM + (n0 + wn + j * 16),
                                    c[i][j], DDIM, wmma::mem_row_major);
}

// ---------------------------------------------------------------------------
extern "C" void kernel_launch(void* const* d_in, const int* in_sizes, int n_in,
                              void* d_out, int out_size) {
    const float* Q = (const float*)d_in[0];
    const float* K = (const float*)d_in[1];
    const float* V = (const float*)d_in[2];
    float* O = (float*)d_out;

    dim3 gQK(LSEQ / BN, LSEQ / BM, NB);    // 32 x 16 x 16
    qk_kernel<<<gQK, 256>>>(Q, K);

    dim3 gSM(LSEQ, NB);                    // 2048 x 16
    softmax_kernel<<<gSM, 256>>>();

    dim3 gPV(DDIM / BN, LSEQ / BM, NB);    // 16 x 16 x 16
    pv_kernel<<<gPV, 256>>>(V, O);
}

// round 4
// speedup vs baseline: 1.7074x; 1.6449x over previous
#include <cuda_runtime.h>
#include <cstdint>

#define NB    16
#define LSEQ  2048
#define DDIM  1024

#define BM 128
#define BN 64
#define BK 16
#define LDA 20     // floats; 80B row stride -> conflict-free LDSM
#define LDV 72     // floats; 288B stride -> conflict-free B LDS in PV

// 256 MB scratch for scores/probs: S[b, q, k]
__device__ float g_S[(size_t)NB * LSEQ * LSEQ];

__device__ __forceinline__ float to_tf32(float x) {
    float r;
    asm("cvt.rna.tf32.f32 %0, %1;" : "=f"(r) : "f"(x));
    return r;
}
__device__ __forceinline__ float4 to_tf32_4(float4 v) {
    v.x = to_tf32(v.x); v.y = to_tf32(v.y); v.z = to_tf32(v.z); v.w = to_tf32(v.w);
    return v;
}
__device__ __forceinline__ uint32_t sptr(const void* p) {
    return (uint32_t)__cvta_generic_to_shared(p);
}
__device__ __forceinline__ void ldsm4(uint32_t r[4], uint32_t a) {
    asm volatile("ldmatrix.sync.aligned.m8n8.x4.shared.b16 {%0,%1,%2,%3}, [%4];"
                 : "=r"(r[0]), "=r"(r[1]), "=r"(r[2]), "=r"(r[3]) : "r"(a));
}
__device__ __forceinline__ void mma8(float c[4], const uint32_t a[4],
                                     uint32_t b0, uint32_t b1) {
    asm volatile("mma.sync.aligned.m16n8k8.row.col.f32.tf32.tf32.f32 "
                 "{%0,%1,%2,%3}, {%4,%5,%6,%7}, {%8,%9}, {%0,%1,%2,%3};"
                 : "+f"(c[0]), "+f"(c[1]), "+f"(c[2]), "+f"(c[3])
                 : "r"(a[0]), "r"(a[1]), "r"(a[2]), "r"(a[3]), "r"(b0), "r"(b1));
}

// ---------------------------------------------------------------------------
// Kernel 1: S = Q @ K^T, raw mma.m16n8k8 tf32 + ldmatrix, double-buffered
// ---------------------------------------------------------------------------
__global__ __launch_bounds__(256) void qk_kernel(const float* __restrict__ Q,
                                                 const float* __restrict__ Kin) {
    const int n0 = blockIdx.x * BN;
    const int m0 = blockIdx.y * BM;
    const int b  = blockIdx.z;
    if (n0 > m0 + BM - 1) return;     // fully masked tile

    __shared__ float As[2][BM * LDA];
    __shared__ float Bs[2][BN * LDA];

    const float* Qb = Q   + (size_t)b * LSEQ * DDIM;
    const float* Kb = Kin + (size_t)b * LSEQ * DDIM;
    float*       Sb = g_S + (size_t)b * LSEQ * LSEQ;

    const int tid = threadIdx.x, lane = tid & 31, wid = tid >> 5;
    const int wm = (wid & 3) * 32, wn = (wid >> 2) * 32;

    // gmem load coords (float4 per thread)
    const int grow = tid >> 2, gch = (tid & 3) * 4;

    // LDSM lane addressing
    // A x4 (16 rows x k8): row = base + (lane&15), col = (lane&16)? 4:0
    const int a_r = lane & 15, a_c = (lane & 16) >> 2;
    // B x4 (two n8 blocks x k8): row = +(lane&7)+((lane&16)?8:0), col=(lane&8)?4:0
    const int b_r = (lane & 7) + ((lane & 16) >> 1), b_c = (lane & 8) >> 1;

    uint32_t a_base[2][2], b_base[2][2];
#pragma unroll
    for (int s = 0; s < 2; s++) {
#pragma unroll
        for (int h = 0; h < 2; h++) {
            a_base[s][h] = sptr(&As[s][(wm + h * 16 + a_r) * LDA + a_c]);
            b_base[s][h] = sptr(&Bs[s][(wn + h * 16 + b_r) * LDA + b_c]);
        }
    }

    float acc[2][4][4];
#pragma unroll
    for (int i = 0; i < 2; i++)
#pragma unroll
        for (int j = 0; j < 4; j++)
#pragma unroll
            for (int e = 0; e < 4; e++) acc[i][j][e] = 0.0f;

    float4 ra0, ra1, rb;
    ra0 = *(const float4*)(Qb + (size_t)(m0 + grow) * DDIM + gch);
    ra1 = *(const float4*)(Qb + (size_t)(m0 + grow + 64) * DDIM + gch);
    rb  = *(const float4*)(Kb + (size_t)(n0 + grow) * DDIM + gch);
    *(float4*)&As[0][grow * LDA + gch]        = to_tf32_4(ra0);
    *(float4*)&As[0][(grow + 64) * LDA + gch] = to_tf32_4(ra1);
    *(float4*)&Bs[0][grow * LDA + gch]        = to_tf32_4(rb);
    __syncthreads();

    const int nt = DDIM / BK;   // 64
    for (int it = 0; it < nt; ++it) {
        const int s = it & 1;
        if (it + 1 < nt) {
            const int d0 = (it + 1) * BK;
            ra0 = *(const float4*)(Qb + (size_t)(m0 + grow) * DDIM + d0 + gch);
            ra1 = *(const float4*)(Qb + (size_t)(m0 + grow + 64) * DDIM + d0 + gch);
            rb  = *(const float4*)(Kb + (size_t)(n0 + grow) * DDIM + d0 + gch);
        }

#pragma unroll
        for (int kk = 0; kk < 2; ++kk) {
            uint32_t af[2][4], bf[2][4];
            ldsm4(af[0], a_base[s][0] + kk * 32);
            ldsm4(af[1], a_base[s][1] + kk * 32);
            ldsm4(bf[0], b_base[s][0] + kk * 32);
            ldsm4(bf[1], b_base[s][1] + kk * 32);
#pragma unroll
            for (int mi = 0; mi < 2; mi++)
#pragma unroll
                for (int ni = 0; ni < 4; ni++)
                    mma8(acc[mi][ni], af[mi],
                         bf[ni >> 1][(ni & 1) * 2], bf[ni >> 1][(ni & 1) * 2 + 1]);
        }

        if (it + 1 < nt) {
            const int s1 = s ^ 1;
            *(float4*)&As[s1][grow * LDA + gch]        = to_tf32_4(ra0);
            *(float4*)&As[s1][(grow + 64) * LDA + gch] = to_tf32_4(ra1);
            *(float4*)&Bs[s1][grow * LDA + gch]        = to_tf32_4(rb);
            __syncthreads();
        }
    }

    const int g = lane >> 2, t2 = (lane & 3) * 2;
#pragma unroll
    for (int mi = 0; mi < 2; mi++)
#pragma unroll
        for (int ni = 0; ni < 4; ni++) {
            float* p = Sb + (size_t)(m0 + wm + mi * 16 + g) * LSEQ + (n0 + wn + ni * 8 + t2);
            *(float2*)p = make_float2(acc[mi][ni][0], acc[mi][ni][1]);
            *(float2*)(p + (size_t)8 * LSEQ) = make_float2(acc[mi][ni][2], acc[mi][ni][3]);
        }
}

// ---------------------------------------------------------------------------
// Kernel 2: row softmax of S/32 with causal mask; masked entries -> exact 0
// ---------------------------------------------------------------------------
__global__ __launch_bounds__(256) void softmax_kernel() {
    const int q = blockIdx.x;
    const int b = blockIdx.y;
    float* row = g_S + ((size_t)b * LSEQ + q) * LSEQ;
    const int tid = threadIdx.x;

    float v[8];
    float mx = -1e30f;
#pragma unroll
    for (int j = 0; j < 8; j++) {
        int i = tid + j * 256;
        float s = (i <= q) ? row[i] * (1.0f / 32.0f) : -1e30f;
        v[j] = s;
        mx = fmaxf(mx, s);
    }
    __shared__ float red[8];
#pragma unroll
    for (int o = 16; o > 0; o >>= 1) mx = fmaxf(mx, __shfl_xor_sync(0xFFFFFFFFu, mx, o));
    if ((tid & 31) == 0) red[tid >> 5] = mx;
    __syncthreads();
    float m = red[0];
#pragma unroll
    for (int w = 1; w < 8; w++) m = fmaxf(m, red[w]);
    __syncthreads();

    float sum = 0.0f;
#pragma unroll
    for (int j = 0; j < 8; j++) {
        float e = exp2f((v[j] - m) * 1.4426950408889634f);
        v[j] = e;
        sum += e;
    }
#pragma unroll
    for (int o = 16; o > 0; o >>= 1) sum += __shfl_xor_sync(0xFFFFFFFFu, sum, o);
    if ((tid & 31) == 0) red[tid >> 5] = sum;
    __syncthreads();
    float tot = 0.0f;
#pragma unroll
    for (int w = 0; w < 8; w++) tot += red[w];
    const float r = 1.0f / tot;
#pragma unroll
    for (int j = 0; j < 8; j++) row[tid + j * 256] = v[j] * r;
}

// ---------------------------------------------------------------------------
// Kernel 3: O = P @ V, raw mma tf32; A via ldmatrix, B via conflict-free LDS
// ---------------------------------------------------------------------------
__global__ __launch_bounds__(256) void pv_kernel(const float* __restrict__ V,
                                                 float* __restrict__ O) {
    const int n0 = blockIdx.x * BN;   // head dim
    const int m0 = blockIdx.y * BM;
    const int b  = blockIdx.z;

    __shared__ float As[2][BM * LDA];
    __shared__ float Vs[2][BK * LDV];   // [k][n], direct copy of V layout

    const float* Pb = g_S + (size_t)b * LSEQ * LSEQ;
    const float* Vb = V   + (size_t)b * LSEQ * DDIM;
    float*       Ob = O   + (size_t)b * LSEQ * DDIM;

    const int tid = threadIdx.x, lane = tid & 31, wid = tid >> 5;
    const int wm = (wid & 3) * 32, wn = (wid >> 2) * 32;

    const int grow = tid >> 2, gch = (tid & 3) * 4;       // P loads
    const int vrow = tid >> 4, vch = (tid & 15) * 4;      // V loads

    const int a_r = lane & 15, a_c = (lane & 16) >> 2;
    uint32_t a_base[2][2];
#pragma unroll
    for (int s = 0; s < 2; s++)
#pragma unroll
        for (int h = 0; h < 2; h++)
            a_base[s][h] = sptr(&As[s][(wm + h * 16 + a_r) * LDA + a_c]);

    // B fragment scalar-LDS coords: b0 = Vs[kk+lane%4][wn+ni*8+lane/4]
    const int bk = lane & 3, bn = lane >> 2;

    float acc[2][4][4];
#pragma unroll
    for (int i = 0; i < 2; i++)
#pragma unroll
        for (int j = 0; j < 4; j++)
#pragma unroll
            for (int e = 0; e < 4; e++) acc[i][j][e] = 0.0f;

    float4 ra0, ra1, rv;
    ra0 = *(const float4*)(Pb + (size_t)(m0 + grow) * LSEQ + gch);
    ra1 = *(const float4*)(Pb + (size_t)(m0 + grow + 64) * LSEQ + gch);
    rv  = *(const float4*)(Vb + (size_t)vrow * DDIM + n0 + vch);
    *(float4*)&As[0][grow * LDA + gch]        = to_tf32_4(ra0);
    *(float4*)&As[0][(grow + 64) * LDA + gch] = to_tf32_4(ra1);
    *(float4*)&Vs[0][vrow * LDV + vch]        = to_tf32_4(rv);
    __syncthreads();

    const int nt = (m0 + BM) / BK;    // P[q,k]==0 for k>q
    for (int it = 0; it < nt; ++it) {
        const int s = it & 1;
        if (it + 1 < nt) {
            const int k0 = (it + 1) * BK;
            ra0 = *(const float4*)(Pb + (size_t)(m0 + grow) * LSEQ + k0 + gch);
            ra1 = *(const float4*)(Pb + (size_t)(m0 + grow + 64) * LSEQ + k0 + gch);
            rv  = *(const float4*)(Vb + (size_t)(k0 + vrow) * DDIM + n0 + vch);
        }

#pragma unroll
        for (int kk = 0; kk < 2; ++kk) {
            uint32_t af[2][4];
            ldsm4(af[0], a_base[s][0] + kk * 32);
            ldsm4(af[1], a_base[s][1] + kk * 32);
            const float* vs0 = &Vs[s][(kk * 8 + bk) * LDV];
            const float* vs1 = vs0 + 4 * LDV;
#pragma unroll
            for (int mi = 0; mi < 2; mi++)
#pragma unroll
                for (int ni = 0; ni < 4; ni++) {
                    uint32_t b0 = __float_as_uint(vs0[wn + ni * 8 + bn]);
                    uint32_t b1 = __float_as_uint(vs1[wn + ni * 8 + bn]);
                    mma8(acc[mi][ni], af[mi], b0, b1);
                }
        }

        if (it + 1 < nt) {
            const int s1 = s ^ 1;
            *(float4*)&As[s1][grow * LDA + gch]        = to_tf32_4(ra0);
            *(float4*)&As[s1][(grow + 64) * LDA + gch] = to_tf32_4(ra1);
            *(float4*)&Vs[s1][vrow * LDV + vch]        = to_tf32_4(rv);
            __syncthreads();
        }
    }

    const int g = lane >> 2, t2 = (lane & 3) * 2;
#pragma unroll
    for (int mi = 0; mi < 2; mi++)
#pragma unroll
        for (int ni = 0; ni < 4; ni++) {
            float* p = Ob + (size_t)(m0 + wm + mi * 16 + g) * DDIM + (n0 + wn + ni * 8 + t2);
            *(float2*)p = make_float2(acc[mi][ni][0], acc[mi][ni][1]);
            *(float2*)(p + (size_t)8 * DDIM) = make_float2(acc[mi][ni][2], acc[mi][ni][3]);
        }
}

// ---------------------------------------------------------------------------
extern "C" void kernel_launch(void* const* d_in, const int* in_sizes, int n_in,
                              void* d_out, int out_size) {
    const float* Q = (const float*)d_in[0];
    const float* K = (const float*)d_in[1];
    const float* V = (const float*)d_in[2];
    float* O = (float*)d_out;

    dim3 gQK(LSEQ / BN, LSEQ / BM, NB);    // 32 x 16 x 16
    qk_kernel<<<gQK, 256>>>(Q, K);

    dim3 gSM(LSEQ, NB);                    // 2048 x 16
    softmax_kernel<<<gSM, 256>>>();

    dim3 gPV(DDIM / BN, LSEQ / BM, NB);    // 16 x 16 x 16
    pv_kernel<<<gPV, 256>>>(V, O);
}